// round 1
// baseline (speedup 1.0000x reference)
#include <cuda_runtime.h>
#include <math.h>

#define HW (1024 * 1024)
#define NPIX4 (HW / 4)          // 262144 = 2^18 float4 per plane
#define TOTAL_GRAD 5709         // 25+81+289+1089+4225

// Scratch (allocation-free: __device__ globals)
__device__ float2       g_grad[TOTAL_GRAD];
__device__ unsigned int g_mink[5];
__device__ unsigned int g_maxk[5];
__device__ float4       g_noise4[NPIX4];   // final noise field, pre-multiplied by mix

// ---------------------------------------------------------------------------
// order-preserving float <-> uint encoding for atomic min/max
// ---------------------------------------------------------------------------
__device__ __forceinline__ unsigned enc(float f) {
    unsigned u = __float_as_uint(f);
    return (u & 0x80000000u) ? ~u : (u | 0x80000000u);
}
__device__ __forceinline__ float dec(unsigned u) {
    return (u & 0x80000000u) ? __uint_as_float(u ^ 0x80000000u)
                             : __uint_as_float(~u);
}

// ---------------------------------------------------------------------------
// raw (un-normalized) perlin value at pixel (i,j) for octave O
// replicates reference exactly:
//   v = i * fl32(res/1023);  P0 = v - floor(v);  cell = i >> (8-O)
// ---------------------------------------------------------------------------
template <int O>
__device__ __forceinline__ float perlin_raw(int i, int j) {
    constexpr int RES = 4 << O;
    constexpr int SH  = 8 - O;
    constexpr int OFFS[5] = {0, 25, 106, 395, 1484};
    const float delta = (float)RES / 1023.0f;   // constant-folded in fp32

    float vy = (float)i * delta;
    float vx = (float)j * delta;
    float P0 = vy - floorf(vy);
    float P1 = vx - floorf(vx);

    int cy = i >> SH;
    int cx = j >> SH;
    const float2* g = g_grad + OFFS[O];
    float2 g00 = g[cy * (RES + 1) + cx];
    float2 g10 = g[(cy + 1) * (RES + 1) + cx];
    float2 g01 = g[cy * (RES + 1) + cx + 1];
    float2 g11 = g[(cy + 1) * (RES + 1) + cx + 1];

    float n00 = P0 * g00.x + P1 * g00.y;
    float n10 = (P0 - 1.0f) * g10.x + P1 * g10.y;
    float n01 = P0 * g01.x + (P1 - 1.0f) * g01.y;
    float n11 = (P0 - 1.0f) * g11.x + (P1 - 1.0f) * g11.y;

    float wy = P0 * P0 * (3.0f - 2.0f * P0);
    float wx = P1 * P1 * (3.0f - 2.0f * P1);
    float n0 = n00 + wy * (n10 - n00);
    float n1 = n01 + wy * (n11 - n01);
    return n0 + wx * (n1 - n0);
}

// ---------------------------------------------------------------------------
// K1: build gradient tables + reset min/max (must happen each replay)
// ---------------------------------------------------------------------------
__global__ void k_setup(const float* __restrict__ a0, const float* __restrict__ a1,
                        const float* __restrict__ a2, const float* __restrict__ a3,
                        const float* __restrict__ a4) {
    int t = blockIdx.x * blockDim.x + threadIdx.x;
    if (blockIdx.x == 0 && threadIdx.x < 5) {
        g_mink[threadIdx.x] = 0xFFFFFFFFu;
        g_maxk[threadIdx.x] = 0u;
    }
    const float* angs[5] = {a0, a1, a2, a3, a4};
    const int cnt[5] = {25, 81, 289, 1089, 4225};
    for (int idx = t; idx < TOTAL_GRAD; idx += gridDim.x * blockDim.x) {
        int o = 0, rem = idx;
        while (o < 4 && rem >= cnt[o]) { rem -= cnt[o]; o++; }
        float a = angs[o][rem];
        float s, c;
        sincosf(a, &s, &c);
        g_grad[idx] = make_float2(c, s);
    }
}

// ---------------------------------------------------------------------------
// K2: global min/max per octave over all 1M pixels
// ---------------------------------------------------------------------------
__global__ void __launch_bounds__(256) k_minmax() {
    int t = blockIdx.x * blockDim.x + threadIdx.x;
    int stride = gridDim.x * blockDim.x;

    float mn[5], mx[5];
#pragma unroll
    for (int o = 0; o < 5; o++) { mn[o] = INFINITY; mx[o] = -INFINITY; }

    for (int pix = t; pix < HW; pix += stride) {
        int i = pix >> 10, j = pix & 1023;
        float r;
        r = perlin_raw<0>(i, j); mn[0] = fminf(mn[0], r); mx[0] = fmaxf(mx[0], r);
        r = perlin_raw<1>(i, j); mn[1] = fminf(mn[1], r); mx[1] = fmaxf(mx[1], r);
        r = perlin_raw<2>(i, j); mn[2] = fminf(mn[2], r); mx[2] = fmaxf(mx[2], r);
        r = perlin_raw<3>(i, j); mn[3] = fminf(mn[3], r); mx[3] = fmaxf(mx[3], r);
        r = perlin_raw<4>(i, j); mn[4] = fminf(mn[4], r); mx[4] = fmaxf(mx[4], r);
    }

    // warp reduce
#pragma unroll
    for (int o = 0; o < 5; o++) {
#pragma unroll
        for (int d = 16; d > 0; d >>= 1) {
            mn[o] = fminf(mn[o], __shfl_xor_sync(0xFFFFFFFFu, mn[o], d));
            mx[o] = fmaxf(mx[o], __shfl_xor_sync(0xFFFFFFFFu, mx[o], d));
        }
    }

    __shared__ float smn[5][8], smx[5][8];
    int w = threadIdx.x >> 5, lane = threadIdx.x & 31;
    if (lane == 0) {
#pragma unroll
        for (int o = 0; o < 5; o++) { smn[o][w] = mn[o]; smx[o][w] = mx[o]; }
    }
    __syncthreads();
    if (threadIdx.x == 0) {
#pragma unroll
        for (int o = 0; o < 5; o++) {
            float a = smn[o][0], b = smx[o][0];
#pragma unroll
            for (int k = 1; k < 8; k++) { a = fminf(a, smn[o][k]); b = fmaxf(b, smx[o][k]); }
            atomicMin(&g_mink[o], enc(a));
            atomicMax(&g_maxk[o], enc(b));
        }
    }
}

// ---------------------------------------------------------------------------
// K3: assemble normalized multi-octave noise, pre-multiplied by mix (4 MB)
// ---------------------------------------------------------------------------
__global__ void __launch_bounds__(256) k_noise(const float* __restrict__ mixp) {
    int pix = blockIdx.x * blockDim.x + threadIdx.x;
    if (pix >= HW) return;
    int i = pix >> 10, j = pix & 1023;

    const float amps[5] = {0.1f, 0.05f, 0.025f, 0.0125f, 0.00625f};
    float acc = 0.0f;
    {
        float mnv = dec(g_mink[0]), mxv = dec(g_maxk[0]);
        float n = (perlin_raw<0>(i, j) - mnv) / (mxv - mnv);
        acc += (n * 2.0f - 1.0f) * amps[0];
    }
    {
        float mnv = dec(g_mink[1]), mxv = dec(g_maxk[1]);
        float n = (perlin_raw<1>(i, j) - mnv) / (mxv - mnv);
        acc += (n * 2.0f - 1.0f) * amps[1];
    }
    {
        float mnv = dec(g_mink[2]), mxv = dec(g_maxk[2]);
        float n = (perlin_raw<2>(i, j) - mnv) / (mxv - mnv);
        acc += (n * 2.0f - 1.0f) * amps[2];
    }
    {
        float mnv = dec(g_mink[3]), mxv = dec(g_maxk[3]);
        float n = (perlin_raw<3>(i, j) - mnv) / (mxv - mnv);
        acc += (n * 2.0f - 1.0f) * amps[3];
    }
    {
        float mnv = dec(g_mink[4]), mxv = dec(g_maxk[4]);
        float n = (perlin_raw<4>(i, j) - mnv) / (mxv - mnv);
        acc += (n * 2.0f - 1.0f) * amps[4];
    }
    ((float*)g_noise4)[pix] = acc * (*mixp);
}

// ---------------------------------------------------------------------------
// K4: HBM-bound streaming apply: out = clip(image + noise, 0, 1)  (float4)
// ---------------------------------------------------------------------------
__global__ void __launch_bounds__(256) k_apply(const float4* __restrict__ img,
                                               float4* __restrict__ out, int n4) {
    int idx = blockIdx.x * blockDim.x + threadIdx.x;
    if (idx >= n4) return;
    float4 nz = g_noise4[idx & (NPIX4 - 1)];   // plane size is 2^18 float4s
    float4 v = img[idx];
    v.x = fminf(fmaxf(v.x + nz.x, 0.0f), 1.0f);
    v.y = fminf(fmaxf(v.y + nz.y, 0.0f), 1.0f);
    v.z = fminf(fmaxf(v.z + nz.z, 0.0f), 1.0f);
    v.w = fminf(fmaxf(v.w + nz.w, 0.0f), 1.0f);
    out[idx] = v;
}

// ---------------------------------------------------------------------------
extern "C" void kernel_launch(void* const* d_in, const int* in_sizes, int n_in,
                              void* d_out, int out_size) {
    const float* image = nullptr;
    const float* mixp  = nullptr;
    const float* ang[5] = {nullptr, nullptr, nullptr, nullptr, nullptr};

    // identify inputs by element count (robust to metadata ordering)
    for (int k = 0; k < n_in; k++) {
        int s = in_sizes[k];
        const float* p = (const float*)d_in[k];
        if      (s == 1)    mixp   = p;
        else if (s == 25)   ang[0] = p;
        else if (s == 81)   ang[1] = p;
        else if (s == 289)  ang[2] = p;
        else if (s == 1089) ang[3] = p;
        else if (s == 4225) ang[4] = p;
        else                image  = p;   // 16*3*1024*1024
    }

    k_setup<<<23, 256>>>(ang[0], ang[1], ang[2], ang[3], ang[4]);
    k_minmax<<<1024, 256>>>();
    k_noise<<<HW / 256, 256>>>(mixp);

    int n4 = out_size / 4;
    k_apply<<<(n4 + 255) / 256, 256>>>((const float4*)image, (float4*)d_out, n4);
}

// round 2
// speedup vs baseline: 1.0340x; 1.0340x over previous
#include <cuda_runtime.h>
#include <math.h>

#define HW (1024 * 1024)
#define NPIX4 (HW / 4)          // 262144 = 2^18 float4 per plane
#define TOTAL_GRAD 5709         // 25+81+289+1089+4225

// Scratch (allocation-free: __device__ globals)
__device__ float2       g_grad[TOTAL_GRAD];
__device__ unsigned int g_mink[5];
__device__ unsigned int g_maxk[5];
__device__ float4       g_noise4[NPIX4];   // final noise field, pre-multiplied by mix

// ---------------------------------------------------------------------------
// order-preserving float <-> uint encoding for atomic min/max
// ---------------------------------------------------------------------------
__device__ __forceinline__ unsigned enc(float f) {
    unsigned u = __float_as_uint(f);
    return (u & 0x80000000u) ? ~u : (u | 0x80000000u);
}
__device__ __forceinline__ float dec(unsigned u) {
    return (u & 0x80000000u) ? __uint_as_float(u ^ 0x80000000u)
                             : __uint_as_float(~u);
}

// ---------------------------------------------------------------------------
// raw (un-normalized) perlin value at pixel (i,j) for octave O
// replicates reference exactly:
//   v = i * fl32(res/1023);  P0 = v - floor(v);  cell = i >> (8-O)
// ---------------------------------------------------------------------------
template <int O>
__device__ __forceinline__ float perlin_raw(int i, int j) {
    constexpr int RES = 4 << O;
    constexpr int SH  = 8 - O;
    constexpr int OFFS[5] = {0, 25, 106, 395, 1484};
    const float delta = (float)RES / 1023.0f;   // constant-folded in fp32

    float vy = (float)i * delta;
    float vx = (float)j * delta;
    float P0 = vy - floorf(vy);
    float P1 = vx - floorf(vx);

    int cy = i >> SH;
    int cx = j >> SH;
    const float2* g = g_grad + OFFS[O];
    float2 g00 = g[cy * (RES + 1) + cx];
    float2 g10 = g[(cy + 1) * (RES + 1) + cx];
    float2 g01 = g[cy * (RES + 1) + cx + 1];
    float2 g11 = g[(cy + 1) * (RES + 1) + cx + 1];

    float n00 = P0 * g00.x + P1 * g00.y;
    float n10 = (P0 - 1.0f) * g10.x + P1 * g10.y;
    float n01 = P0 * g01.x + (P1 - 1.0f) * g01.y;
    float n11 = (P0 - 1.0f) * g11.x + (P1 - 1.0f) * g11.y;

    float wy = P0 * P0 * (3.0f - 2.0f * P0);
    float wx = P1 * P1 * (3.0f - 2.0f * P1);
    float n0 = n00 + wy * (n10 - n00);
    float n1 = n01 + wy * (n11 - n01);
    return n0 + wx * (n1 - n0);
}

// ---------------------------------------------------------------------------
// K1: build gradient tables + reset min/max (must happen each replay)
// ---------------------------------------------------------------------------
__global__ void k_setup(const float* __restrict__ a0, const float* __restrict__ a1,
                        const float* __restrict__ a2, const float* __restrict__ a3,
                        const float* __restrict__ a4) {
    int t = blockIdx.x * blockDim.x + threadIdx.x;
    if (blockIdx.x == 0 && threadIdx.x < 5) {
        g_mink[threadIdx.x] = 0xFFFFFFFFu;
        g_maxk[threadIdx.x] = 0u;
    }
    const float* angs[5] = {a0, a1, a2, a3, a4};
    const int cnt[5] = {25, 81, 289, 1089, 4225};
    for (int idx = t; idx < TOTAL_GRAD; idx += gridDim.x * blockDim.x) {
        int o = 0, rem = idx;
        while (o < 4 && rem >= cnt[o]) { rem -= cnt[o]; o++; }
        float a = angs[o][rem];
        float s, c;
        sincosf(a, &s, &c);
        g_grad[idx] = make_float2(c, s);
    }
}

// ---------------------------------------------------------------------------
// K2: global min/max per octave over all 1M pixels
// ---------------------------------------------------------------------------
__global__ void __launch_bounds__(256) k_minmax() {
    int t = blockIdx.x * blockDim.x + threadIdx.x;
    int stride = gridDim.x * blockDim.x;

    float mn[5], mx[5];
#pragma unroll
    for (int o = 0; o < 5; o++) { mn[o] = INFINITY; mx[o] = -INFINITY; }

    for (int pix = t; pix < HW; pix += stride) {
        int i = pix >> 10, j = pix & 1023;
        float r;
        r = perlin_raw<0>(i, j); mn[0] = fminf(mn[0], r); mx[0] = fmaxf(mx[0], r);
        r = perlin_raw<1>(i, j); mn[1] = fminf(mn[1], r); mx[1] = fmaxf(mx[1], r);
        r = perlin_raw<2>(i, j); mn[2] = fminf(mn[2], r); mx[2] = fmaxf(mx[2], r);
        r = perlin_raw<3>(i, j); mn[3] = fminf(mn[3], r); mx[3] = fmaxf(mx[3], r);
        r = perlin_raw<4>(i, j); mn[4] = fminf(mn[4], r); mx[4] = fmaxf(mx[4], r);
    }

    // warp reduce
#pragma unroll
    for (int o = 0; o < 5; o++) {
#pragma unroll
        for (int d = 16; d > 0; d >>= 1) {
            mn[o] = fminf(mn[o], __shfl_xor_sync(0xFFFFFFFFu, mn[o], d));
            mx[o] = fmaxf(mx[o], __shfl_xor_sync(0xFFFFFFFFu, mx[o], d));
        }
    }

    __shared__ float smn[5][8], smx[5][8];
    int w = threadIdx.x >> 5, lane = threadIdx.x & 31;
    if (lane == 0) {
#pragma unroll
        for (int o = 0; o < 5; o++) { smn[o][w] = mn[o]; smx[o][w] = mx[o]; }
    }
    __syncthreads();
    if (threadIdx.x == 0) {
#pragma unroll
        for (int o = 0; o < 5; o++) {
            float a = smn[o][0], b = smx[o][0];
#pragma unroll
            for (int k = 1; k < 8; k++) { a = fminf(a, smn[o][k]); b = fmaxf(b, smx[o][k]); }
            atomicMin(&g_mink[o], enc(a));
            atomicMax(&g_maxk[o], enc(b));
        }
    }
}

// ---------------------------------------------------------------------------
// K3: assemble normalized multi-octave noise, pre-multiplied by mix (4 MB)
// One float4 (4 pixels, same row) per thread; row-dependent Perlin terms CSE.
// ---------------------------------------------------------------------------
__global__ void __launch_bounds__(256) k_noise(const float* __restrict__ mixp) {
    int p4 = blockIdx.x * blockDim.x + threadIdx.x;
    if (p4 >= NPIX4) return;
    int pix = p4 << 2;
    int i = pix >> 10, j0 = pix & 1023;

    float mixv = *mixp;

    // decode min/max + fold normalization into scale/bias:
    //   out = ((raw-mn)/(mx-mn)*2-1)*amp  -> raw*s + b  is NOT bit-identical,
    // so keep the literal form but hoist the decodes.
    float mnv[5], mxv[5];
#pragma unroll
    for (int o = 0; o < 5; o++) { mnv[o] = dec(g_mink[o]); mxv[o] = dec(g_maxk[o]); }
    const float amps[5] = {0.1f, 0.05f, 0.025f, 0.0125f, 0.00625f};

    float4 r;
    float* rp = &r.x;
#pragma unroll
    for (int k = 0; k < 4; k++) {
        int j = j0 + k;
        float acc = 0.0f;
        {
            float n = (perlin_raw<0>(i, j) - mnv[0]) / (mxv[0] - mnv[0]);
            acc += (n * 2.0f - 1.0f) * amps[0];
        }
        {
            float n = (perlin_raw<1>(i, j) - mnv[1]) / (mxv[1] - mnv[1]);
            acc += (n * 2.0f - 1.0f) * amps[1];
        }
        {
            float n = (perlin_raw<2>(i, j) - mnv[2]) / (mxv[2] - mnv[2]);
            acc += (n * 2.0f - 1.0f) * amps[2];
        }
        {
            float n = (perlin_raw<3>(i, j) - mnv[3]) / (mxv[3] - mnv[3]);
            acc += (n * 2.0f - 1.0f) * amps[3];
        }
        {
            float n = (perlin_raw<4>(i, j) - mnv[4]) / (mxv[4] - mnv[4]);
            acc += (n * 2.0f - 1.0f) * amps[4];
        }
        rp[k] = acc * mixv;
    }
    g_noise4[p4] = r;
}

// ---------------------------------------------------------------------------
// K4: HBM-bound streaming apply: out = clip(image + noise, 0, 1)
// 4 float4 per thread, block-strided (each LDG fully coalesced),
// loads front-batched for MLP. __ldcs/__stcs keep noise plane L2-resident.
// ---------------------------------------------------------------------------
#define VPT 4
__global__ void __launch_bounds__(256) k_apply(const float4* __restrict__ img,
                                               float4* __restrict__ out, int n4) {
    int base = blockIdx.x * (256 * VPT) + threadIdx.x;

    if (base + 3 * 256 < n4) {
        float4 v0 = __ldcs(img + base);
        float4 v1 = __ldcs(img + base + 256);
        float4 v2 = __ldcs(img + base + 512);
        float4 v3 = __ldcs(img + base + 768);
        float4 n0 = g_noise4[(base)       & (NPIX4 - 1)];
        float4 n1 = g_noise4[(base + 256) & (NPIX4 - 1)];
        float4 n2 = g_noise4[(base + 512) & (NPIX4 - 1)];
        float4 n3 = g_noise4[(base + 768) & (NPIX4 - 1)];

        v0.x = fminf(fmaxf(v0.x + n0.x, 0.0f), 1.0f);
        v0.y = fminf(fmaxf(v0.y + n0.y, 0.0f), 1.0f);
        v0.z = fminf(fmaxf(v0.z + n0.z, 0.0f), 1.0f);
        v0.w = fminf(fmaxf(v0.w + n0.w, 0.0f), 1.0f);
        v1.x = fminf(fmaxf(v1.x + n1.x, 0.0f), 1.0f);
        v1.y = fminf(fmaxf(v1.y + n1.y, 0.0f), 1.0f);
        v1.z = fminf(fmaxf(v1.z + n1.z, 0.0f), 1.0f);
        v1.w = fminf(fmaxf(v1.w + n1.w, 0.0f), 1.0f);
        v2.x = fminf(fmaxf(v2.x + n2.x, 0.0f), 1.0f);
        v2.y = fminf(fmaxf(v2.y + n2.y, 0.0f), 1.0f);
        v2.z = fminf(fmaxf(v2.z + n2.z, 0.0f), 1.0f);
        v2.w = fminf(fmaxf(v2.w + n2.w, 0.0f), 1.0f);
        v3.x = fminf(fmaxf(v3.x + n3.x, 0.0f), 1.0f);
        v3.y = fminf(fmaxf(v3.y + n3.y, 0.0f), 1.0f);
        v3.z = fminf(fmaxf(v3.z + n3.z, 0.0f), 1.0f);
        v3.w = fminf(fmaxf(v3.w + n3.w, 0.0f), 1.0f);

        __stcs(out + base,       v0);
        __stcs(out + base + 256, v1);
        __stcs(out + base + 512, v2);
        __stcs(out + base + 768, v3);
    } else {
        // tail (not taken for 16*3*1024*1024, kept for safety)
        for (int k = 0; k < VPT; k++) {
            int idx = base + k * 256;
            if (idx >= n4) break;
            float4 nz = g_noise4[idx & (NPIX4 - 1)];
            float4 v = __ldcs(img + idx);
            v.x = fminf(fmaxf(v.x + nz.x, 0.0f), 1.0f);
            v.y = fminf(fmaxf(v.y + nz.y, 0.0f), 1.0f);
            v.z = fminf(fmaxf(v.z + nz.z, 0.0f), 1.0f);
            v.w = fminf(fmaxf(v.w + nz.w, 0.0f), 1.0f);
            __stcs(out + idx, v);
        }
    }
}

// ---------------------------------------------------------------------------
extern "C" void kernel_launch(void* const* d_in, const int* in_sizes, int n_in,
                              void* d_out, int out_size) {
    const float* image = nullptr;
    const float* mixp  = nullptr;
    const float* ang[5] = {nullptr, nullptr, nullptr, nullptr, nullptr};

    // identify inputs by element count (robust to metadata ordering)
    for (int k = 0; k < n_in; k++) {
        int s = in_sizes[k];
        const float* p = (const float*)d_in[k];
        if      (s == 1)    mixp   = p;
        else if (s == 25)   ang[0] = p;
        else if (s == 81)   ang[1] = p;
        else if (s == 289)  ang[2] = p;
        else if (s == 1089) ang[3] = p;
        else if (s == 4225) ang[4] = p;
        else                image  = p;   // 16*3*1024*1024
    }

    k_setup<<<23, 256>>>(ang[0], ang[1], ang[2], ang[3], ang[4]);
    k_minmax<<<1024, 256>>>();
    k_noise<<<NPIX4 / 256, 256>>>(mixp);

    int n4 = out_size / 4;
    int blocks = (n4 + 256 * VPT - 1) / (256 * VPT);
    k_apply<<<blocks, 256>>>((const float4*)image, (float4*)d_out, n4);
}

// round 3
// speedup vs baseline: 1.1936x; 1.1544x over previous
#include <cuda_runtime.h>
#include <math.h>

#define HW (1024 * 1024)
#define NPIX4 (HW / 4)          // 262144 = 2^18 float4 per plane
#define NRUNS (HW / 16)         // 65536 16-pixel runs
#define TOTAL_GRAD 5709         // 25+81+289+1089+4225

// Scratch (allocation-free: __device__ globals)
__device__ float2       g_grad[TOTAL_GRAD];
__device__ unsigned int g_mink[5];
__device__ unsigned int g_maxk[5];
__device__ float4       g_noise4[NPIX4];   // final noise, pre-multiplied by mix

// ---------------------------------------------------------------------------
// order-preserving float <-> uint encoding for atomic min/max
// ---------------------------------------------------------------------------
__device__ __forceinline__ unsigned enc(float f) {
    unsigned u = __float_as_uint(f);
    return (u & 0x80000000u) ? ~u : (u | 0x80000000u);
}
__device__ __forceinline__ float dec(unsigned u) {
    return (u & 0x80000000u) ? __uint_as_float(u ^ 0x80000000u)
                             : __uint_as_float(~u);
}

// ---------------------------------------------------------------------------
// Per-run (16 aligned pixels, same row => single cell in every octave)
// hoisted Perlin constants.  n(j) = t0 + wx*t1,
//   t0 = C0 + P1*D0,  t1 = E + P1*F
// ---------------------------------------------------------------------------
struct RunConst { float C0, D0, E, F; };

template <int O>
__device__ __forceinline__ RunConst run_const(int i, int j0) {
    constexpr int RES = 4 << O;
    constexpr int SH  = 8 - O;
    constexpr int OFFS[5] = {0, 25, 106, 395, 1484};
    const float delta = (float)RES / 1023.0f;

    float vy = (float)i * delta;
    float P0 = vy - floorf(vy);
    float wy = P0 * P0 * (3.0f - 2.0f * P0);

    int cy = i >> SH, cx = j0 >> SH;
    const float2* g = g_grad + OFFS[O];
    float2 g00 = g[cy * (RES + 1) + cx];
    float2 g10 = g[(cy + 1) * (RES + 1) + cx];
    float2 g01 = g[cy * (RES + 1) + cx + 1];
    float2 g11 = g[(cy + 1) * (RES + 1) + cx + 1];

    // n00 = A0 + P1*g00.y ; n10 = A1 + P1*g10.y
    // n01 = B0 + P1*g01.y ; n11 = B1 + P1*g11.y
    float A0 = P0 * g00.x;
    float A1 = (P0 - 1.0f) * g10.x;
    float B0 = P0 * g01.x - g01.y;
    float B1 = (P0 - 1.0f) * g11.x - g11.y;

    float C0 = A0 + wy * (A1 - A0);
    float D0 = g00.y + wy * (g10.y - g00.y);
    float C1 = B0 + wy * (B1 - B0);
    float D1 = g01.y + wy * (g11.y - g01.y);

    RunConst rc;
    rc.C0 = C0; rc.D0 = D0; rc.E = C1 - C0; rc.F = D1 - D0;
    return rc;
}

template <int O>
__device__ __forceinline__ float run_eval(const RunConst& rc, int j) {
    constexpr int RES = 4 << O;
    const float delta = (float)RES / 1023.0f;
    float vx = (float)j * delta;
    float P1 = vx - floorf(vx);
    float wx = P1 * P1 * (3.0f - 2.0f * P1);
    float t0 = fmaf(P1, rc.D0, rc.C0);
    float t1 = fmaf(P1, rc.F, rc.E);
    return fmaf(wx, t1, t0);
}

// ---------------------------------------------------------------------------
// K1: build gradient tables + reset min/max (must happen each replay)
// ---------------------------------------------------------------------------
__global__ void k_setup(const float* __restrict__ a0, const float* __restrict__ a1,
                        const float* __restrict__ a2, const float* __restrict__ a3,
                        const float* __restrict__ a4) {
    int t = blockIdx.x * blockDim.x + threadIdx.x;
    if (blockIdx.x == 0 && threadIdx.x < 5) {
        g_mink[threadIdx.x] = 0xFFFFFFFFu;
        g_maxk[threadIdx.x] = 0u;
    }
    const float* angs[5] = {a0, a1, a2, a3, a4};
    const int cnt[5] = {25, 81, 289, 1089, 4225};
    for (int idx = t; idx < TOTAL_GRAD; idx += gridDim.x * blockDim.x) {
        int o = 0, rem = idx;
        while (o < 4 && rem >= cnt[o]) { rem -= cnt[o]; o++; }
        float a = angs[o][rem];
        float s, c;
        sincosf(a, &s, &c);
        g_grad[idx] = make_float2(c, s);
    }
}

// ---------------------------------------------------------------------------
// K2: global min/max per octave. One thread = one 16-pixel run.
// ---------------------------------------------------------------------------
__global__ void __launch_bounds__(256) k_minmax() {
    int t = blockIdx.x * blockDim.x + threadIdx.x;   // 0..65535
    int i  = t >> 6;
    int j0 = (t & 63) << 4;

    RunConst r0 = run_const<0>(i, j0);
    RunConst r1 = run_const<1>(i, j0);
    RunConst r2 = run_const<2>(i, j0);
    RunConst r3 = run_const<3>(i, j0);
    RunConst r4 = run_const<4>(i, j0);

    float mn[5], mx[5];
#pragma unroll
    for (int o = 0; o < 5; o++) { mn[o] = INFINITY; mx[o] = -INFINITY; }

#pragma unroll
    for (int k = 0; k < 16; k++) {
        int j = j0 + k;
        float n;
        n = run_eval<0>(r0, j); mn[0] = fminf(mn[0], n); mx[0] = fmaxf(mx[0], n);
        n = run_eval<1>(r1, j); mn[1] = fminf(mn[1], n); mx[1] = fmaxf(mx[1], n);
        n = run_eval<2>(r2, j); mn[2] = fminf(mn[2], n); mx[2] = fmaxf(mx[2], n);
        n = run_eval<3>(r3, j); mn[3] = fminf(mn[3], n); mx[3] = fmaxf(mx[3], n);
        n = run_eval<4>(r4, j); mn[4] = fminf(mn[4], n); mx[4] = fmaxf(mx[4], n);
    }

    // warp reduce
#pragma unroll
    for (int o = 0; o < 5; o++) {
#pragma unroll
        for (int d = 16; d > 0; d >>= 1) {
            mn[o] = fminf(mn[o], __shfl_xor_sync(0xFFFFFFFFu, mn[o], d));
            mx[o] = fmaxf(mx[o], __shfl_xor_sync(0xFFFFFFFFu, mx[o], d));
        }
    }

    __shared__ float smn[5][8], smx[5][8];
    int w = threadIdx.x >> 5, lane = threadIdx.x & 31;
    if (lane == 0) {
#pragma unroll
        for (int o = 0; o < 5; o++) { smn[o][w] = mn[o]; smx[o][w] = mx[o]; }
    }
    __syncthreads();
    if (threadIdx.x == 0) {
#pragma unroll
        for (int o = 0; o < 5; o++) {
            float a = smn[o][0], b = smx[o][0];
#pragma unroll
            for (int k = 1; k < 8; k++) { a = fminf(a, smn[o][k]); b = fmaxf(b, smx[o][k]); }
            atomicMin(&g_mink[o], enc(a));
            atomicMax(&g_maxk[o], enc(b));
        }
    }
}

// ---------------------------------------------------------------------------
// K3: normalized multi-octave noise * mix.  One thread = one 16-pixel run.
// Normalization folded to scale/bias:  contrib = n*s_o + b_o,  B = sum(b_o).
// ---------------------------------------------------------------------------
__global__ void __launch_bounds__(256) k_noise(const float* __restrict__ mixp) {
    int t = blockIdx.x * blockDim.x + threadIdx.x;   // 0..65535
    int i  = t >> 6;
    int j0 = (t & 63) << 4;

    float mixv = *mixp;
    const float amps[5] = {0.1f, 0.05f, 0.025f, 0.0125f, 0.00625f};
    float s[5], B = 0.0f;
#pragma unroll
    for (int o = 0; o < 5; o++) {
        float mnv = dec(g_mink[o]), mxv = dec(g_maxk[o]);
        float inv = 1.0f / (mxv - mnv);
        float am = amps[o] * mixv;
        s[o] = 2.0f * am * inv;
        B += am * (-2.0f * mnv * inv - 1.0f);
    }

    RunConst r0 = run_const<0>(i, j0);
    RunConst r1 = run_const<1>(i, j0);
    RunConst r2 = run_const<2>(i, j0);
    RunConst r3 = run_const<3>(i, j0);
    RunConst r4 = run_const<4>(i, j0);

    float vals[16];
#pragma unroll
    for (int k = 0; k < 16; k++) {
        int j = j0 + k;
        float acc = B;
        acc = fmaf(run_eval<0>(r0, j), s[0], acc);
        acc = fmaf(run_eval<1>(r1, j), s[1], acc);
        acc = fmaf(run_eval<2>(r2, j), s[2], acc);
        acc = fmaf(run_eval<3>(r3, j), s[3], acc);
        acc = fmaf(run_eval<4>(r4, j), s[4], acc);
        vals[k] = acc;
    }

    int p4 = t << 2;   // 4 consecutive float4 per run
#pragma unroll
    for (int q = 0; q < 4; q++) {
        g_noise4[p4 + q] = make_float4(vals[4 * q], vals[4 * q + 1],
                                       vals[4 * q + 2], vals[4 * q + 3]);
    }
}

// ---------------------------------------------------------------------------
// K4: HBM-bound streaming apply: out = clip(image + noise, 0, 1)
// 4 float4 per thread, block-strided, loads front-batched, streaming hints.
// ---------------------------------------------------------------------------
#define VPT 4
__global__ void __launch_bounds__(256) k_apply(const float4* __restrict__ img,
                                               float4* __restrict__ out, int n4) {
    int base = blockIdx.x * (256 * VPT) + threadIdx.x;

    if (base + 3 * 256 < n4) {
        float4 v0 = __ldcs(img + base);
        float4 v1 = __ldcs(img + base + 256);
        float4 v2 = __ldcs(img + base + 512);
        float4 v3 = __ldcs(img + base + 768);
        float4 n0 = g_noise4[(base)       & (NPIX4 - 1)];
        float4 n1 = g_noise4[(base + 256) & (NPIX4 - 1)];
        float4 n2 = g_noise4[(base + 512) & (NPIX4 - 1)];
        float4 n3 = g_noise4[(base + 768) & (NPIX4 - 1)];

        v0.x = fminf(fmaxf(v0.x + n0.x, 0.0f), 1.0f);
        v0.y = fminf(fmaxf(v0.y + n0.y, 0.0f), 1.0f);
        v0.z = fminf(fmaxf(v0.z + n0.z, 0.0f), 1.0f);
        v0.w = fminf(fmaxf(v0.w + n0.w, 0.0f), 1.0f);
        v1.x = fminf(fmaxf(v1.x + n1.x, 0.0f), 1.0f);
        v1.y = fminf(fmaxf(v1.y + n1.y, 0.0f), 1.0f);
        v1.z = fminf(fmaxf(v1.z + n1.z, 0.0f), 1.0f);
        v1.w = fminf(fmaxf(v1.w + n1.w, 0.0f), 1.0f);
        v2.x = fminf(fmaxf(v2.x + n2.x, 0.0f), 1.0f);
        v2.y = fminf(fmaxf(v2.y + n2.y, 0.0f), 1.0f);
        v2.z = fminf(fmaxf(v2.z + n2.z, 0.0f), 1.0f);
        v2.w = fminf(fmaxf(v2.w + n2.w, 0.0f), 1.0f);
        v3.x = fminf(fmaxf(v3.x + n3.x, 0.0f), 1.0f);
        v3.y = fminf(fmaxf(v3.y + n3.y, 0.0f), 1.0f);
        v3.z = fminf(fmaxf(v3.z + n3.z, 0.0f), 1.0f);
        v3.w = fminf(fmaxf(v3.w + n3.w, 0.0f), 1.0f);

        __stcs(out + base,       v0);
        __stcs(out + base + 256, v1);
        __stcs(out + base + 512, v2);
        __stcs(out + base + 768, v3);
    } else {
        for (int k = 0; k < VPT; k++) {
            int idx = base + k * 256;
            if (idx >= n4) break;
            float4 nz = g_noise4[idx & (NPIX4 - 1)];
            float4 v = __ldcs(img + idx);
            v.x = fminf(fmaxf(v.x + nz.x, 0.0f), 1.0f);
            v.y = fminf(fmaxf(v.y + nz.y, 0.0f), 1.0f);
            v.z = fminf(fmaxf(v.z + nz.z, 0.0f), 1.0f);
            v.w = fminf(fmaxf(v.w + nz.w, 0.0f), 1.0f);
            __stcs(out + idx, v);
        }
    }
}

// ---------------------------------------------------------------------------
extern "C" void kernel_launch(void* const* d_in, const int* in_sizes, int n_in,
                              void* d_out, int out_size) {
    const float* image = nullptr;
    const float* mixp  = nullptr;
    const float* ang[5] = {nullptr, nullptr, nullptr, nullptr, nullptr};

    for (int k = 0; k < n_in; k++) {
        int s = in_sizes[k];
        const float* p = (const float*)d_in[k];
        if      (s == 1)    mixp   = p;
        else if (s == 25)   ang[0] = p;
        else if (s == 81)   ang[1] = p;
        else if (s == 289)  ang[2] = p;
        else if (s == 1089) ang[3] = p;
        else if (s == 4225) ang[4] = p;
        else                image  = p;   // 16*3*1024*1024
    }

    k_setup<<<23, 256>>>(ang[0], ang[1], ang[2], ang[3], ang[4]);
    k_minmax<<<NRUNS / 256, 256>>>();
    k_noise<<<NRUNS / 256, 256>>>(mixp);

    int n4 = out_size / 4;
    int blocks = (n4 + 256 * VPT - 1) / (256 * VPT);
    k_apply<<<blocks, 256>>>((const float4*)image, (float4*)d_out, n4);
}